// round 6
// baseline (speedup 1.0000x reference)
#include <cuda_runtime.h>
#include <cstdint>

// Problem constants
#define BATCH 1024
#define SEQ   512
#define NF    64
#define H     128
#define G4    512
#define NOUT  128

// Kernel config
#define M     8
#define NCTA  128
#define NTHR  512
#define RES0  12              // kg0 resident W_hh rows: k in [0,12)
#define RES1  12              // kg1 resident W_hh rows: k in [56,68)
#define KS0   56              // kg0 h-rows [0,56), kg1 [56,128)

// smem layout (floats)
#define OFF_WIH   0                           // [64][512]
#define OFF_WHH   (64 * G4)                   // [24][512]: rows 0..11 (kg0), 56..67 (kg1)
#define OFF_XD    (OFF_WHH + 24 * G4)         // [2][64][8]
#define OFF_HD    (OFF_XD + 2 * NF * M)       // [128][8]
#define OFF_GB    (OFF_HD + H * M)            // [512][9]
#define OFF_PART  (OFF_GB + G4 * 9)           // [8][256] ull
#define SMEM_FLOATS (OFF_PART + 8 * 256 * 2)  // 55808
#define SMEM_BYTES  (SMEM_FLOATS * 4)         // 223232

typedef unsigned long long ull;

__device__ float g_WihT[NF * G4];     // [f][c]
__device__ float g_WhhT[H * G4];      // [k][c]
__device__ float g_WoutT[H * NOUT];   // [k][oc]

// ---------------- packed f32x2 helpers ----------------
__device__ __forceinline__ void ffma2(ull& acc, ull a, ull b) {
    asm("fma.rn.f32x2 %0, %1, %2, %0;" : "+l"(acc) : "l"(a), "l"(b));
}
__device__ __forceinline__ ull fadd2(ull a, ull b) {
    ull r; asm("add.rn.f32x2 %0, %1, %2;" : "=l"(r) : "l"(a), "l"(b)); return r;
}
__device__ __forceinline__ ull pack2(float lo, float hi) {
    ull r; asm("mov.b64 %0, {%1, %2};" : "=l"(r) : "f"(lo), "f"(hi)); return r;
}
__device__ __forceinline__ void unpack2(ull v, float& lo, float& hi) {
    asm("mov.b64 {%0, %1}, %2;" : "=f"(lo), "=f"(hi) : "l"(v));
}
__device__ __forceinline__ void dup2(ull w2, ull& d0, ull& d1) {
    asm("{\n\t"
        ".reg .f32 w0, w1;\n\t"
        "mov.b64 {w0, w1}, %2;\n\t"
        "mov.b64 %0, {w0, w0};\n\t"
        "mov.b64 %1, {w1, w1};\n\t"
        "}" : "=l"(d0), "=l"(d1) : "l"(w2));
}

// ---------------- activations ----------------
__device__ __forceinline__ float ex2f(float x) { float r; asm("ex2.approx.f32 %0, %1;" : "=f"(r) : "f"(x)); return r; }
__device__ __forceinline__ float rcpf(float x) { float r; asm("rcp.approx.f32 %0, %1;" : "=f"(r) : "f"(x)); return r; }
__device__ __forceinline__ float sigmf(float x) {
    return rcpf(1.0f + ex2f(-1.4426950408889634f * x));
}
__device__ __forceinline__ float tanhf_acc(float x) {
    return fmaf(2.0f, rcpf(1.0f + ex2f(-2.8853900817779268f * x)), -1.0f);
}
__device__ __forceinline__ float act(float v, bool isTanh) {
    return isTanh ? tanhf_acc(v) : sigmf(v);
}

// ---------------- one-time weight transpose ----------------
__global__ void prep_kernel(const float* __restrict__ W_ih,
                            const float* __restrict__ W_hh,
                            const float* __restrict__ W_out) {
    int idx = blockIdx.x * blockDim.x + threadIdx.x;
    if (idx < (NF + H) * G4) {
        int k = idx / G4;
        int c = idx - k * G4;
        if (k < NF) g_WihT[idx]               = W_ih[c * NF + k];
        else        g_WhhT[(k - NF) * G4 + c] = W_hh[c * H + (k - NF)];
    } else {
        int j = idx - (NF + H) * G4;
        if (j < H * NOUT) {
            int k = j >> 7, oc = j & 127;
            g_WoutT[k * NOUT + oc] = W_out[oc * H + k];
        }
    }
}

// matvec micro-step: acc[c][rowpairs] += rows * dup(w_c)
#define STEPW(W2, HSRC)                                                 \
    do {                                                                \
        ull d0, d1; dup2((W2), d0, d1);                                 \
        ulonglong2 hA = *(const ulonglong2*)(HSRC);                     \
        ulonglong2 hB = *(const ulonglong2*)((HSRC) + 4);               \
        ffma2(a00, hA.x, d0); ffma2(a01, hA.y, d0);                     \
        ffma2(a02, hB.x, d0); ffma2(a03, hB.y, d0);                     \
        ffma2(a10, hA.x, d1); ffma2(a11, hA.y, d1);                     \
        ffma2(a12, hB.x, d1); ffma2(a13, hB.y, d1);                     \
    } while (0)

// ---------------- persistent fused LSTM kernel ----------------
__global__ void __launch_bounds__(NTHR, 1)
lstm_kernel(const float* __restrict__ x,
            const float* __restrict__ b_ih, const float* __restrict__ b_hh,
            const float* __restrict__ b_out,
            float* __restrict__ out)
{
    extern __shared__ float sm[];
    float* Wih  = sm + OFF_WIH;
    float* Whh  = sm + OFF_WHH;
    float* xd   = sm + OFF_XD;
    float* hd   = sm + OFF_HD;
    float* gbuf = sm + OFF_GB;
    ull*   part = (ull*)(sm + OFF_PART);

    const int tid = threadIdx.x;
    const int b0  = blockIdx.x * M;

    const int cp = tid & 255;
    const int c0 = 2 * cp;
    const int kg = tid >> 8;

    // ---- stage resident weights ----
    {
        const float4* s = (const float4*)g_WihT;
        float4*       d = (float4*)Wih;
        #pragma unroll
        for (int i = 0; i < (NF * G4 / 4) / NTHR; ++i) d[tid + i * NTHR] = s[tid + i * NTHR];
    }
    {   // resident W_hh rows: [0,12) -> sm rows 0..11 ; [56,68) -> sm rows 12..23
        float4* d = (float4*)Whh;
        const float4* s0 = (const float4*)(g_WhhT);
        const float4* s1 = (const float4*)(g_WhhT + 56 * G4);
        for (int i = tid; i < RES0 * G4 / 4; i += NTHR) d[i] = s0[i];
        for (int i = tid; i < RES1 * G4 / 4; i += NTHR) d[RES0 * G4 / 4 + i] = s1[i];
    }
    for (int i = tid; i < H * M; i += NTHR) hd[i] = 0.0f;

    // x loader identity: lf = tid>>3 (0..63), lr = tid&7
    const int lf = tid >> 3, lr = tid & 7;
    const float* xp = x + ((size_t)(b0 + lr) * SEQ) * NF + lf;
    xd[tid] = xp[0];                       // xd[0][lf][lr], contiguous STS

    const ull bias0 = (kg == 0) ? pack2(b_ih[c0] + b_hh[c0], b_ih[c0] + b_hh[c0]) : 0ull;
    const ull bias1 = (kg == 0) ? pack2(b_ih[c0 + 1] + b_hh[c0 + 1], b_ih[c0 + 1] + b_hh[c0 + 1]) : 0ull;
    const bool isT = ((c0 >> 7) == 2);

    // phase-2 identity
    const int hc = tid & 127;
    const int a2 = (tid >> 7) * 2;         // rows a2, a2+1
    float cst0 = 0.f, cst1 = 0.f;

    __syncthreads();

    for (int t = 0; t < SEQ; ++t) {
        // prefetch x(t+1) (consumed ~3000 cyc later)
        float xpre = 0.f;
        const bool doPre = (t + 1 < SEQ);
        if (doPre) xpre = __ldg(xp + (size_t)(t + 1) * NF);

        ull a00 = bias0, a01 = bias0, a02 = bias0, a03 = bias0;
        ull a10 = bias1, a11 = bias1, a12 = bias1, a13 = bias1;

        // ---- x-part (both groups 32 rows; xd(t) ready) ----
        const float* xsb = xd + (t & 1) * (NF * M);
        if (kg == 0) {
            #pragma unroll 8
            for (int j = 0; j < 32; ++j) {
                ull w2 = *(const ull*)(Wih + j * G4 + c0);
                STEPW(w2, xsb + j * M);
            }
        } else {
            #pragma unroll 8
            for (int j = 32; j < NF; ++j) {
                ull w2 = *(const ull*)(Wih + j * G4 + c0);
                STEPW(w2, xsb + j * M);
            }
        }

        // ---- phase 2 for step t-1 (hidden under x-part skew) ----
        if (t > 0) {
            const float* gi = gbuf + hc * 9;
            const float* gf = gi + 128 * 9;
            const float* gg = gi + 256 * 9;
            const float* go = gi + 384 * 9;
            float i0 = gi[a2],     f0 = gf[a2],     gv0 = gg[a2],     o0 = go[a2];
            float i1 = gi[a2 + 1], f1 = gf[a2 + 1], gv1 = gg[a2 + 1], o1 = go[a2 + 1];
            cst0 = fmaf(f0, cst0, i0 * gv0);
            cst1 = fmaf(f1, cst1, i1 * gv1);
            float h0 = o0 * tanhf_acc(cst0);
            float h1 = o1 * tanhf_acc(cst1);
            *(ull*)(hd + hc * M + a2) = pack2(h0, h1);
        }
        __syncthreads();   // B1: hd(t-1) complete

        // ---- h-part ----
        if (kg == 0) {
            #pragma unroll
            for (int k = 0; k < RES0; ++k) {             // rows 0..11 resident
                ull w2 = *(const ull*)(Whh + k * G4 + c0);
                STEPW(w2, hd + k * M);
            }
            #pragma unroll 8
            for (int k = RES0; k < KS0; ++k) {           // rows 12..55 streamed
                ull w2 = __ldg((const ull*)(g_WhhT + k * G4) + cp);
                STEPW(w2, hd + k * M);
            }
        } else {
            #pragma unroll
            for (int k = 0; k < RES1; ++k) {             // rows 56..67 resident
                ull w2 = *(const ull*)(Whh + (RES0 + k) * G4 + c0);
                STEPW(w2, hd + (KS0 + k) * M);
            }
            #pragma unroll 8
            for (int k = KS0 + RES1; k < H; ++k) {       // rows 68..127 streamed
                ull w2 = __ldg((const ull*)(g_WhhT + k * G4) + cp);
                STEPW(w2, hd + k * M);
            }
        }

        if (kg == 1) {
            ull* pb = part + cp;
            pb[0 * 256] = a00; pb[1 * 256] = a01; pb[2 * 256] = a02; pb[3 * 256] = a03;
            pb[4 * 256] = a10; pb[5 * 256] = a11; pb[6 * 256] = a12; pb[7 * 256] = a13;
        }
        // stage x(t+1)
        if (doPre) xd[((t + 1) & 1) * (NF * M) + tid] = xpre;

        __syncthreads();   // B2: partials visible

        if (kg == 0) {
            const ull* pb = part + cp;
            a00 = fadd2(a00, pb[0 * 256]); a01 = fadd2(a01, pb[1 * 256]);
            a02 = fadd2(a02, pb[2 * 256]); a03 = fadd2(a03, pb[3 * 256]);
            a10 = fadd2(a10, pb[4 * 256]); a11 = fadd2(a11, pb[5 * 256]);
            a12 = fadd2(a12, pb[6 * 256]); a13 = fadd2(a13, pb[7 * 256]);

            float v0, v1;
            float* g0 = gbuf + c0 * 9;
            float* g1 = g0 + 9;
            unpack2(a00, v0, v1); g0[0] = act(v0, isT); g0[1] = act(v1, isT);
            unpack2(a01, v0, v1); g0[2] = act(v0, isT); g0[3] = act(v1, isT);
            unpack2(a02, v0, v1); g0[4] = act(v0, isT); g0[5] = act(v1, isT);
            unpack2(a03, v0, v1); g0[6] = act(v0, isT); g0[7] = act(v1, isT);
            unpack2(a10, v0, v1); g1[0] = act(v0, isT); g1[1] = act(v1, isT);
            unpack2(a11, v0, v1); g1[2] = act(v0, isT); g1[3] = act(v1, isT);
            unpack2(a12, v0, v1); g1[4] = act(v0, isT); g1[5] = act(v1, isT);
            unpack2(a13, v0, v1); g1[6] = act(v0, isT); g1[7] = act(v1, isT);
        }
        __syncthreads();   // B3: gbuf(t) ready
    }

    // final phase 2 (t = SEQ-1)
    {
        const float* gi = gbuf + hc * 9;
        const float* gf = gi + 128 * 9;
        const float* gg = gi + 256 * 9;
        const float* go = gi + 384 * 9;
        float i0 = gi[a2],     f0 = gf[a2],     gv0 = gg[a2],     o0 = go[a2];
        float i1 = gi[a2 + 1], f1 = gf[a2 + 1], gv1 = gg[a2 + 1], o1 = go[a2 + 1];
        cst0 = fmaf(f0, cst0, i0 * gv0);
        cst1 = fmaf(f1, cst1, i1 * gv1);
        hd[hc * M + a2]     = o0 * tanhf_acc(cst0);
        hd[hc * M + a2 + 1] = o1 * tanhf_acc(cst1);
    }
    __syncthreads();

    // output projection
    {
        const int oc = tid & 127;
        const int rr = tid >> 7;           // rows rr and rr+4
        float acc0 = b_out[oc], acc1 = acc0;
        const float* wt = g_WoutT + oc;
        #pragma unroll 8
        for (int k = 0; k < H; ++k) {
            float w = __ldg(wt + k * NOUT);
            acc0 = fmaf(w, hd[k * M + rr], acc0);
            acc1 = fmaf(w, hd[k * M + rr + 4], acc1);
        }
        out[(size_t)(b0 + rr) * NOUT + oc]     = acc0;
        out[(size_t)(b0 + rr + 4) * NOUT + oc] = acc1;
    }
}

extern "C" void kernel_launch(void* const* d_in, const int* in_sizes, int n_in,
                              void* d_out, int out_size)
{
    const float* x     = (const float*)d_in[0];
    const float* W_ih  = (const float*)d_in[1];
    const float* W_hh  = (const float*)d_in[2];
    const float* b_ih  = (const float*)d_in[3];
    const float* b_hh  = (const float*)d_in[4];
    const float* W_out = (const float*)d_in[5];
    const float* b_out = (const float*)d_in[6];
    float* out = (float*)d_out;

    const int prep_n = (NF + H) * G4 + H * NOUT;
    prep_kernel<<<(prep_n + 255) / 256, 256>>>(W_ih, W_hh, W_out);

    cudaFuncSetAttribute(lstm_kernel,
                         cudaFuncAttributeMaxDynamicSharedMemorySize, SMEM_BYTES);
    lstm_kernel<<<NCTA, NTHR, SMEM_BYTES>>>(x, b_ih, b_hh, b_out, out);
}

// round 7
// speedup vs baseline: 1.0141x; 1.0141x over previous
#include <cuda_runtime.h>
#include <cstdint>

// Problem constants
#define BATCH 1024
#define SEQ   512
#define NF    64
#define H     128
#define G4    512
#define NOUT  128

// Kernel config
#define M     8
#define NCTA  128
#define NTHR  768
#define RES   10               // resident W_hh rows per h-kgroup

// smem layout (floats)
#define OFF_WIH   0                            // [64][512]
#define OFF_WHH   (64 * G4)                    // [20][512]: rows 0..9 = Whh[0..9], 10..19 = Whh[64..73]
#define OFF_XD    (OFF_WHH + 2 * RES * G4)     // [2][64][8]
#define OFF_HD    (OFF_XD + 2 * NF * M)        // [128][8]
#define OFF_GB    (OFF_HD + H * M)             // [512][9]
#define OFF_PART  (OFF_GB + G4 * 9)            // [16][256] ull
#define SMEM_FLOATS (OFF_PART + 16 * 256 * 2)  // 57856
#define SMEM_BYTES  (SMEM_FLOATS * 4)          // 231424

typedef unsigned long long ull;

__device__ float g_WihT[NF * G4];     // [f][c]
__device__ float g_WhhT[H * G4];      // [k][c]
__device__ float g_WoutT[H * NOUT];   // [k][oc]

// ---------------- packed f32x2 helpers ----------------
__device__ __forceinline__ void ffma2(ull& acc, ull a, ull b) {
    asm("fma.rn.f32x2 %0, %1, %2, %0;" : "+l"(acc) : "l"(a), "l"(b));
}
__device__ __forceinline__ ull fadd2(ull a, ull b) {
    ull r; asm("add.rn.f32x2 %0, %1, %2;" : "=l"(r) : "l"(a), "l"(b)); return r;
}
__device__ __forceinline__ ull pack2(float lo, float hi) {
    ull r; asm("mov.b64 %0, {%1, %2};" : "=l"(r) : "f"(lo), "f"(hi)); return r;
}
__device__ __forceinline__ void unpack2(ull v, float& lo, float& hi) {
    asm("mov.b64 {%0, %1}, %2;" : "=f"(lo), "=f"(hi) : "l"(v));
}
__device__ __forceinline__ void dup2(ull w2, ull& d0, ull& d1) {
    asm("{\n\t"
        ".reg .f32 w0, w1;\n\t"
        "mov.b64 {w0, w1}, %2;\n\t"
        "mov.b64 %0, {w0, w0};\n\t"
        "mov.b64 %1, {w1, w1};\n\t"
        "}" : "=l"(d0), "=l"(d1) : "l"(w2));
}

// ---------------- activations ----------------
__device__ __forceinline__ float ex2f(float x) { float r; asm("ex2.approx.f32 %0, %1;" : "=f"(r) : "f"(x)); return r; }
__device__ __forceinline__ float rcpf(float x) { float r; asm("rcp.approx.f32 %0, %1;" : "=f"(r) : "f"(x)); return r; }
__device__ __forceinline__ float sigmf(float x) {
    return rcpf(1.0f + ex2f(-1.4426950408889634f * x));
}
__device__ __forceinline__ float tanhf_acc(float x) {
    return fmaf(2.0f, rcpf(1.0f + ex2f(-2.8853900817779268f * x)), -1.0f);
}
__device__ __forceinline__ float act(float v, bool isTanh) {
    return isTanh ? tanhf_acc(v) : sigmf(v);
}

// ---------------- one-time weight transpose ----------------
__global__ void prep_kernel(const float* __restrict__ W_ih,
                            const float* __restrict__ W_hh,
                            const float* __restrict__ W_out) {
    int idx = blockIdx.x * blockDim.x + threadIdx.x;
    if (idx < (NF + H) * G4) {
        int k = idx / G4;
        int c = idx - k * G4;
        if (k < NF) g_WihT[idx]               = W_ih[c * NF + k];
        else        g_WhhT[(k - NF) * G4 + c] = W_hh[c * H + (k - NF)];
    } else {
        int j = idx - (NF + H) * G4;
        if (j < H * NOUT) {
            int k = j >> 7, oc = j & 127;
            g_WoutT[k * NOUT + oc] = W_out[oc * H + k];
        }
    }
}

// matvec micro-step: acc[2 cols][4 rowpairs] += rows * dup(w_c)
#define STEPW(W2, HSRC)                                                 \
    do {                                                                \
        ull d0, d1; dup2((W2), d0, d1);                                 \
        ulonglong2 hA = *(const ulonglong2*)(HSRC);                     \
        ulonglong2 hB = *(const ulonglong2*)((HSRC) + 4);               \
        ffma2(a00, hA.x, d0); ffma2(a01, hA.y, d0);                     \
        ffma2(a02, hB.x, d0); ffma2(a03, hB.y, d0);                     \
        ffma2(a10, hA.x, d1); ffma2(a11, hA.y, d1);                     \
        ffma2(a12, hB.x, d1); ffma2(a13, hB.y, d1);                     \
    } while (0)

// ---------------- persistent fused LSTM kernel ----------------
__global__ void __launch_bounds__(NTHR, 1)
lstm_kernel(const float* __restrict__ x,
            const float* __restrict__ b_ih, const float* __restrict__ b_hh,
            const float* __restrict__ b_out,
            float* __restrict__ out)
{
    extern __shared__ float sm[];
    float* Wih  = sm + OFF_WIH;
    float* Whh  = sm + OFF_WHH;
    float* xd   = sm + OFF_XD;
    float* hd   = sm + OFF_HD;
    float* gbuf = sm + OFF_GB;
    ull*   part = (ull*)(sm + OFF_PART);

    const int tid = threadIdx.x;
    const int b0  = blockIdx.x * M;

    const int cp = tid & 255;
    const int c0 = 2 * cp;
    const int kg = tid >> 8;            // 0,1,2

    // ---- stage resident weights ----
    {
        const float4* s = (const float4*)g_WihT;
        float4*       d = (float4*)Wih;
        for (int i = tid; i < NF * G4 / 4; i += NTHR) d[i] = s[i];
    }
    {   // rows 0..9 -> Whh[0..9]; rows 10..19 -> Whh[64..73]
        float4* d = (float4*)Whh;
        const float4* s0 = (const float4*)(g_WhhT);
        const float4* s1 = (const float4*)(g_WhhT + 64 * G4);
        for (int i = tid; i < RES * G4 / 4; i += NTHR) {
            d[i]                 = s0[i];
            d[RES * G4 / 4 + i]  = s1[i];
        }
    }
    for (int i = tid; i < H * M; i += NTHR) hd[i] = 0.0f;

    // x loader identity (tid < 256): features 2fp,2fp+1, row r
    const int fp = tid >> 3;            // 0..31 (valid when tid<256)
    const int lr = tid & 7;
    const float* xp = x + ((size_t)(b0 + lr) * SEQ) * NF + 2 * (fp & 31);
    if (tid < 256) {
        float2 v = *(const float2*)xp;  // t = 0
        xd[(2 * fp) * M + lr]     = v.x;
        xd[(2 * fp + 1) * M + lr] = v.y;
    }

    const ull bias0 = (kg == 0) ? pack2(b_ih[c0] + b_hh[c0], b_ih[c0] + b_hh[c0]) : 0ull;
    const ull bias1 = (kg == 0) ? pack2(b_ih[c0 + 1] + b_hh[c0 + 1], b_ih[c0 + 1] + b_hh[c0 + 1]) : 0ull;
    const bool isT = ((c0 >> 7) == 2);

    // phase-2 identity (tid < 512)
    const int hc = tid & 127;
    const int a2 = ((tid >> 7) & 3) * 2;
    float cst0 = 0.f, cst1 = 0.f;

    __syncthreads();

    for (int t = 0; t < SEQ; ++t) {
        // prefetch x(t+1)
        float2 xpre = make_float2(0.f, 0.f);
        const bool doPre = (tid < 256) && (t + 1 < SEQ);
        if (doPre) xpre = *(const float2*)(xp + (size_t)(t + 1) * NF);

        ull a00 = bias0, a01 = bias0, a02 = bias0, a03 = bias0;
        ull a10 = bias1, a11 = bias1, a12 = bias1, a13 = bias1;

        const float* xsb = xd + (t & 1) * (NF * M);

        if (kg == 0) {
            // x-part: 64 rows, weights resident
            #pragma unroll 4
            for (int j = 0; j < NF; ++j) {
                ull w2 = *(const ull*)(Wih + j * G4 + c0);
                STEPW(w2, xsb + j * M);
            }
        } else if (kg == 1) {
            // h rows [0,10) resident
            #pragma unroll
            for (int k = 0; k < RES; ++k) {
                ull w2 = *(const ull*)(Whh + k * G4 + c0);
                STEPW(w2, hd + k * M);
            }
            // h rows [10,64) streamed
            const ull* wg = (const ull*)(g_WhhT + RES * G4) + cp;
            #pragma unroll 4
            for (int k = RES; k < 64; ++k) {
                ull w2 = __ldg(wg); wg += (G4 / 2);
                STEPW(w2, hd + k * M);
            }
        } else {
            // h rows [64,74) resident
            #pragma unroll
            for (int k = 0; k < RES; ++k) {
                ull w2 = *(const ull*)(Whh + (RES + k) * G4 + c0);
                STEPW(w2, hd + (64 + k) * M);
            }
            // h rows [74,128) streamed
            const ull* wg = (const ull*)(g_WhhT + (64 + RES) * G4) + cp;
            #pragma unroll 4
            for (int k = 64 + RES; k < H; ++k) {
                ull w2 = __ldg(wg); wg += (G4 / 2);
                STEPW(w2, hd + k * M);
            }
        }

        if (kg != 0) {
            ull* pb = part + (kg - 1) * 8 * 256 + cp;
            pb[0 * 256] = a00; pb[1 * 256] = a01; pb[2 * 256] = a02; pb[3 * 256] = a03;
            pb[4 * 256] = a10; pb[5 * 256] = a11; pb[6 * 256] = a12; pb[7 * 256] = a13;
        }
        // stage x(t+1) into the other buffer
        if (doPre) {
            float* xn = xd + ((t + 1) & 1) * (NF * M);
            xn[(2 * fp) * M + lr]     = xpre.x;
            xn[(2 * fp + 1) * M + lr] = xpre.y;
        }
        __syncthreads();   // B1: partials visible

        if (kg == 0) {
            const ull* p1 = part + cp;
            const ull* p2 = part + 8 * 256 + cp;
            a00 = fadd2(fadd2(a00, p1[0 * 256]), p2[0 * 256]);
            a01 = fadd2(fadd2(a01, p1[1 * 256]), p2[1 * 256]);
            a02 = fadd2(fadd2(a02, p1[2 * 256]), p2[2 * 256]);
            a03 = fadd2(fadd2(a03, p1[3 * 256]), p2[3 * 256]);
            a10 = fadd2(fadd2(a10, p1[4 * 256]), p2[4 * 256]);
            a11 = fadd2(fadd2(a11, p1[5 * 256]), p2[5 * 256]);
            a12 = fadd2(fadd2(a12, p1[6 * 256]), p2[6 * 256]);
            a13 = fadd2(fadd2(a13, p1[7 * 256]), p2[7 * 256]);

            float v0, v1;
            float* g0 = gbuf + c0 * 9;
            float* g1 = g0 + 9;
            unpack2(a00, v0, v1); g0[0] = act(v0, isT); g0[1] = act(v1, isT);
            unpack2(a01, v0, v1); g0[2] = act(v0, isT); g0[3] = act(v1, isT);
            unpack2(a02, v0, v1); g0[4] = act(v0, isT); g0[5] = act(v1, isT);
            unpack2(a03, v0, v1); g0[6] = act(v0, isT); g0[7] = act(v1, isT);
            unpack2(a10, v0, v1); g1[0] = act(v0, isT); g1[1] = act(v1, isT);
            unpack2(a11, v0, v1); g1[2] = act(v0, isT); g1[3] = act(v1, isT);
            unpack2(a12, v0, v1); g1[4] = act(v0, isT); g1[5] = act(v1, isT);
            unpack2(a13, v0, v1); g1[6] = act(v0, isT); g1[7] = act(v1, isT);
        }
        __syncthreads();   // B2: gbuf(t) ready

        // phase 2 (tid < 512): update (hc, rows a2, a2+1)
        if (tid < 512) {
            const float* gi = gbuf + hc * 9;
            const float* gf = gi + 128 * 9;
            const float* gg = gi + 256 * 9;
            const float* go = gi + 384 * 9;
            float i0 = gi[a2],     f0 = gf[a2],     gv0 = gg[a2],     o0 = go[a2];
            float i1 = gi[a2 + 1], f1 = gf[a2 + 1], gv1 = gg[a2 + 1], o1 = go[a2 + 1];
            cst0 = fmaf(f0, cst0, i0 * gv0);
            cst1 = fmaf(f1, cst1, i1 * gv1);
            float h0 = o0 * tanhf_acc(cst0);
            float h1 = o1 * tanhf_acc(cst1);
            *(ull*)(hd + hc * M + a2) = pack2(h0, h1);
        }
        __syncthreads();   // B3: hd(t) ready
    }

    // output projection (tid < 512)
    if (tid < 512) {
        const int oc = tid & 127;
        const int rr = tid >> 7;           // rows rr and rr+4
        float acc0 = b_out[oc], acc1 = acc0;
        const float* wt = g_WoutT + oc;
        #pragma unroll 8
        for (int k = 0; k < H; ++k) {
            float w = __ldg(wt + k * NOUT);
            acc0 = fmaf(w, hd[k * M + rr], acc0);
            acc1 = fmaf(w, hd[k * M + rr + 4], acc1);
        }
        out[(size_t)(b0 + rr) * NOUT + oc]     = acc0;
        out[(size_t)(b0 + rr + 4) * NOUT + oc] = acc1;
    }
}

extern "C" void kernel_launch(void* const* d_in, const int* in_sizes, int n_in,
                              void* d_out, int out_size)
{
    const float* x     = (const float*)d_in[0];
    const float* W_ih  = (const float*)d_in[1];
    const float* W_hh  = (const float*)d_in[2];
    const float* b_ih  = (const float*)d_in[3];
    const float* b_hh  = (const float*)d_in[4];
    const float* W_out = (const float*)d_in[5];
    const float* b_out = (const float*)d_in[6];
    float* out = (float*)d_out;

    const int prep_n = (NF + H) * G4 + H * NOUT;
    prep_kernel<<<(prep_n + 255) / 256, 256>>>(W_ih, W_hh, W_out);

    cudaFuncSetAttribute(lstm_kernel,
                         cudaFuncAttributeMaxDynamicSharedMemorySize, SMEM_BYTES);
    lstm_kernel<<<NCTA, NTHR, SMEM_BYTES>>>(x, b_ih, b_hh, b_out, out);
}